// round 17
// baseline (speedup 1.0000x reference)
#include <cuda_runtime.h>
#include <cuda_fp16.h>
#include <cstdint>

#define BB 2
#define SS 2048
#define EE 1024
#define HH 16
#define DD 64
#define MM (BB*SS)
#define GSTR 40            // gemm smem row stride (halves)
#define GS (128*GSTR)      // halves per gemm tile array
#define KSTR 72            // attn smem row stride (halves)
#define ATILE (64*KSTR)    // halves per 64-row attn sub-tile
#define QTILE (128*KSTR)   // halves per attn Q tile array
#define LOG2E 1.4426950408889634f

// ---------------- scratch (device globals: allocation-free rule) ------------
__device__ half g_x[MM*EE];                 // x, fp16
__device__ half g_att[MM*EE];               // attention out, fp16
__device__ half g_wq[EE*EE], g_wk[EE*EE], g_wv[EE*EE], g_wo[EE*EE];
__device__ half g_Q[BB*HH*SS*DD];           // pre-scaled by log2e/8
__device__ half g_K[BB*HH*SS*DD];
__device__ half g_V[BB*HH*SS*DD];

// ---------------- helpers ---------------------------------------------------
__device__ __forceinline__ uint32_t smem_u32(const void* p) {
    uint32_t a;
    asm("{ .reg .u64 t; cvta.to.shared.u64 t, %1; cvt.u32.u64 %0, t; }" : "=r"(a) : "l"(p));
    return a;
}
__device__ __forceinline__ void ldsm_x4(uint32_t& r0, uint32_t& r1, uint32_t& r2,
                                        uint32_t& r3, uint32_t addr) {
    asm volatile("ldmatrix.sync.aligned.m8n8.x4.shared.b16 {%0,%1,%2,%3}, [%4];"
                 : "=r"(r0), "=r"(r1), "=r"(r2), "=r"(r3) : "r"(addr));
}
__device__ __forceinline__ void ldsm_x4t(uint32_t& r0, uint32_t& r1, uint32_t& r2,
                                         uint32_t& r3, uint32_t addr) {
    asm volatile("ldmatrix.sync.aligned.m8n8.x4.trans.shared.b16 {%0,%1,%2,%3}, [%4];"
                 : "=r"(r0), "=r"(r1), "=r"(r2), "=r"(r3) : "r"(addr));
}
__device__ __forceinline__ void mma_f16(float* c, const uint32_t* a,
                                        uint32_t b0, uint32_t b1) {
    asm volatile(
        "mma.sync.aligned.m16n8k16.row.col.f32.f16.f16.f32 "
        "{%0,%1,%2,%3}, {%4,%5,%6,%7}, {%8,%9}, {%0,%1,%2,%3};"
        : "+f"(c[0]), "+f"(c[1]), "+f"(c[2]), "+f"(c[3])
        : "r"(a[0]), "r"(a[1]), "r"(a[2]), "r"(a[3]), "r"(b0), "r"(b1));
}
__device__ __forceinline__ void cpa16(uint32_t dst, const void* src) {
    asm volatile("cp.async.cg.shared.global [%0], [%1], 16;" :: "r"(dst), "l"(src));
}
#define CP_COMMIT() asm volatile("cp.async.commit_group;" ::: "memory")
#define CP_WAIT1()  asm volatile("cp.async.wait_group 1;" ::: "memory")
#define CP_WAIT0()  asm volatile("cp.async.wait_group 0;" ::: "memory")

__device__ __forceinline__ float ex2(float x) {
    float r;
    asm("ex2.approx.f32 %0, %1;" : "=f"(r) : "f"(x));
    return r;
}
__device__ __forceinline__ uint32_t pack_h2(float a, float b) {
    __half2 h = __floats2half2_rn(a, b);
    return *(uint32_t*)&h;
}

// ---------------- fused fp32 -> fp16 conversion (x + 4 weights) -------------
__global__ __launch_bounds__(256) void conv_fused(
    const float* __restrict__ x,  const float* __restrict__ Wq,
    const float* __restrict__ Wk, const float* __restrict__ Wv,
    const float* __restrict__ Wo)
{
    const int i = blockIdx.x * blockDim.x + threadIdx.x;
    const float* src; half* dst; int off;
    if (i < (1 << 20)) {
        src = x; dst = g_x; off = i;
    } else {
        const int j = i - (1 << 20);
        const int w = j >> 18;
        off = j & ((1 << 18) - 1);
        src = (w == 0) ? Wq : (w == 1) ? Wk : (w == 2) ? Wv : Wo;
        dst = (w == 0) ? g_wq : (w == 1) ? g_wk : (w == 2) ? g_wv : g_wo;
    }
    float4 v = ((const float4*)src)[off];
    ((uint2*)dst)[off] = make_uint2(pack_h2(v.x, v.y), pack_h2(v.z, v.w));
}

// ---------------------------------------------------------------------------
// 1-term fp16 GEMM core: 128x128 CTA tile, BK=32, 3-stage cp.async pipeline.
// FULL chunk fragment hoist: 12 LDSM (all A + all B) issued back-to-back,
// then 32 dependency-free MMAs.
// ---------------------------------------------------------------------------
__device__ __forceinline__ void gemm_body(
    const half* __restrict__ A, const half* __restrict__ B,
    const float* __restrict__ bias, float* __restrict__ Cout, int sel,
    half* smg, int row0, int col0)
{
    const int t    = threadIdx.x;
    const int warp = t >> 5;
    const int lane = t & 31;
    const int wm   = (warp >> 2) * 64;
    const int wn   = (warp & 3) * 32;

    float acc[4][4][4];
#pragma unroll
    for (int mi = 0; mi < 4; mi++)
#pragma unroll
        for (int ni = 0; ni < 4; ni++)
#pragma unroll
            for (int k = 0; k < 4; k++) acc[mi][ni][k] = 0.f;

    const uint32_t sbase = smem_u32(smg);
    const int lr = t >> 1;
    const int lh = (t & 1) * 16;
    const half* pA = A + (size_t)(row0 + lr) * EE + lh;
    const half* pB = B + (size_t)(col0 + lr) * EE + lh;
    const uint32_t drow = (uint32_t)(lr * GSTR + lh) * 2;

    auto load_stage = [&](int c, int s) {
        const uint32_t sb = sbase + (uint32_t)(s * 2 * GS) * 2 + drow;
        const int ko = c * 32;
        cpa16(sb,          pA + ko);  cpa16(sb + 16,          pA + ko + 8);
        cpa16(sb + GS*2,   pB + ko);  cpa16(sb + GS*2 + 16,   pB + ko + 8);
    };

    load_stage(0, 0); CP_COMMIT();
    load_stage(1, 1); CP_COMMIT();

    const int a_row  = lane & 15;
    const int a_half = (lane >> 4) << 3;

    for (int c = 0; c < 32; c++) {
        if (c < 31) { CP_WAIT1(); } else { CP_WAIT0(); }
        __syncthreads();
        if (c + 2 < 32) { load_stage(c + 2, (c + 2) % 3); CP_COMMIT(); }

        const uint32_t uA = sbase + (uint32_t)((c % 3) * 2 * GS) * 2;
        const uint32_t uB = uA + GS * 2;

        // ---- hoist ALL fragments for this chunk ----
        uint32_t bF[2][4][2];                       // 16 regs
#pragma unroll
        for (int ks = 0; ks < 2; ks++) {
#pragma unroll
            for (int u = 0; u < 2; u++) {
                const uint32_t bo = (uint32_t)((wn + u*16 + a_row) * GSTR + ks*16 + a_half) * 2;
                uint32_t r0, r1, r2, r3;
                ldsm_x4(r0, r1, r2, r3, uB + bo);
                bF[ks][2*u][0] = r0; bF[ks][2*u][1] = r2;
                bF[ks][2*u+1][0] = r1; bF[ks][2*u+1][1] = r3;
            }
        }
        uint32_t aF[4][2][4];                       // 32 regs
#pragma unroll
        for (int mi = 0; mi < 4; mi++) {
            const uint32_t ao = (uint32_t)((wm + mi*16 + a_row) * GSTR + a_half) * 2;
            ldsm_x4(aF[mi][0][0], aF[mi][0][1], aF[mi][0][2], aF[mi][0][3], uA + ao);
            ldsm_x4(aF[mi][1][0], aF[mi][1][1], aF[mi][1][2], aF[mi][1][3], uA + ao + 16*2);
        }
        // ---- 32 dependency-free MMAs ----
#pragma unroll
        for (int mi = 0; mi < 4; mi++)
#pragma unroll
            for (int ks = 0; ks < 2; ks++)
#pragma unroll
                for (int ni = 0; ni < 4; ni++)
                    mma_f16(acc[mi][ni], aF[mi][ks], bF[ks][ni][0], bF[ks][ni][1]);
    }

    // ---- epilogue ----
    const int gr = lane >> 2;
    const int gc = (lane & 3) * 2;
    const float qs = (sel == 0) ? (0.125f * LOG2E) : 1.f;
#pragma unroll
    for (int mi = 0; mi < 4; mi++) {
#pragma unroll
        for (int ni = 0; ni < 4; ni++) {
#pragma unroll
            for (int half_ = 0; half_ < 2; half_++) {
                const int m = row0 + wm + mi*16 + gr + half_*8;
                const int n = col0 + wn + ni*8 + gc;
                float v0 = acc[mi][ni][half_*2+0] + bias[n];
                float v1 = acc[mi][ni][half_*2+1] + bias[n+1];
                if (sel < 0) {
                    *(float2*)&Cout[(size_t)m * EE + n] = make_float2(v0, v1);
                } else {
                    const int b = m >> 11, s = m & 2047;
                    const int hh = n >> 6, d = n & 63;
                    const size_t idx = ((((size_t)b*HH + hh)*SS + s)*DD + d) >> 1;
                    half* outp = (sel == 0) ? g_Q : (sel == 1) ? g_K : g_V;
                    ((uint32_t*)outp)[idx] = pack_h2(v0 * qs, v1 * qs);
                }
            }
        }
    }
}

// Fused QKV projection: gridDim.z = 3 selects weight/bias/output.
__global__ __launch_bounds__(256, 2) void gemm_qkv(
    const float* __restrict__ bq, const float* __restrict__ bk,
    const float* __restrict__ bv)
{
    extern __shared__ half smg[];
    const int z = blockIdx.z;
    const half*  B    = (z == 0) ? g_wq : (z == 1) ? g_wk : g_wv;
    const float* bias = (z == 0) ? bq   : (z == 1) ? bk   : bv;
    gemm_body(g_x, B, bias, nullptr, z, smg, blockIdx.x * 128, blockIdx.y * 128);
}

__global__ __launch_bounds__(256, 2) void gemm_out(
    const float* __restrict__ bo, float* __restrict__ Cout)
{
    extern __shared__ half smg[];
    gemm_body(g_att, g_wo, bo, Cout, -1, smg, blockIdx.x * 128, blockIdx.y * 128);
}

// ---------------------------------------------------------------------------
// Tensor-core flash attention (pure fp16 MMAs, base-2 online softmax).
// grid (S/128, B*H), 256 threads (8 warps x 16 query rows), 2 CTAs/SM.
// Q fragments held in registers across the whole loop (loop-invariant).
// ---------------------------------------------------------------------------
__global__ __launch_bounds__(256, 2) void attn_mma()
{
    extern __shared__ half sma[];
    const int t    = threadIdx.x;
    const int warp = t >> 5;
    const int lane = t & 31;
    const int bh   = blockIdx.y;
    const int q0   = blockIdx.x * 128;
    const int b    = bh >> 4;
    const int h    = bh & 15;

    const uint32_t sbase = smem_u32(sma);
    const uint32_t uQ = sbase;
    const size_t bhoff = (size_t)bh * SS * DD;

    // ---- Q tile -> smem via cp.async ----
    {
        const int qrow = t >> 1;
        const int qch  = (t & 1) * 32;
        const size_t src = bhoff + (size_t)(q0 + qrow)*DD + qch;
        const uint32_t dst = sbase + (uint32_t)(qrow * KSTR + qch) * 2;
#pragma unroll
        for (int c = 0; c < 32; c += 8)
            cpa16(dst + c*2, g_Q + src + c);
    }

    // ---- K/V 128-key stage loaders ----
    const int lrow = t >> 1;
    const int lchk = (t & 1) * 32;
    const uint32_t ddst = (uint32_t)(lrow * KSTR + lchk) * 2;
    auto load_kv = [&](int kb, int s) {
        const size_t src = bhoff + (size_t)(kb*128 + lrow)*DD + lchk;
        const uint32_t sb = sbase + (uint32_t)(QTILE + s * 4 * ATILE) * 2 + ddst;
#pragma unroll
        for (int c = 0; c < 32; c += 8) {
            cpa16(sb + c*2,               g_K + src + c);
            cpa16(sb + 2*ATILE*2 + c*2,   g_V + src + c);
        }
    };

    float m0 = -1e30f, m1 = -1e30f, l0 = 0.f, l1 = 0.f;
    float oc[8][4];
#pragma unroll
    for (int ni = 0; ni < 8; ni++)
#pragma unroll
        for (int k = 0; k < 4; k++) oc[ni][k] = 0.f;

    load_kv(0, 0);      // Q + stage 0 in one group
    CP_COMMIT();

    const int a_row  = lane & 15;
    const int a_half = (lane >> 4) << 3;
    const int g      = lane >> 3;
    const int t_row  = (g & 1)*8 + (lane & 7);
    const int t_col  = (g >> 1)*8;

    // ---- wait for Q + stage 0, then hoist Q fragments (loop-invariant) ----
    CP_WAIT0();
    __syncthreads();
    uint32_t qF[4][4];
#pragma unroll
    for (int ks = 0; ks < 4; ks++) {
        const uint32_t qo = (uint32_t)((warp*16 + a_row) * KSTR + ks*16 + a_half) * 2;
        ldsm_x4(qF[ks][0], qF[ks][1], qF[ks][2], qF[ks][3], uQ + qo);
    }

    for (int kb = 0; kb < SS/128; kb++) {
        if (kb > 0) { CP_WAIT0(); __syncthreads(); }
        if (kb + 1 < SS/128) { load_kv(kb + 1, (kb + 1) & 1); CP_COMMIT(); }

        const uint32_t uK0 = sbase + (uint32_t)(QTILE + (kb & 1) * 4 * ATILE) * 2;
        const uint32_t uV0 = uK0 + 2*ATILE*2;

#pragma unroll
        for (int p = 0; p < 2; p++) {
            const uint32_t uK = uK0 + p * ATILE * 2;
            const uint32_t uV = uV0 + p * ATILE * 2;

            // ---- S = Q K^T (log2 domain): batch 4 K-ldsm, then 8 MMAs ----
            float sc[8][4];
#pragma unroll
            for (int ni = 0; ni < 8; ni++)
#pragma unroll
                for (int k = 0; k < 4; k++) sc[ni][k] = 0.f;

#pragma unroll
            for (int ks = 0; ks < 4; ks++) {
                uint32_t kF[4][4];
#pragma unroll
                for (int u = 0; u < 4; u++) {
                    const uint32_t bo = (uint32_t)((u*16 + a_row) * KSTR + ks*16 + a_half) * 2;
                    ldsm_x4(kF[u][0], kF[u][1], kF[u][2], kF[u][3], uK + bo);
                }
#pragma unroll
                for (int u = 0; u < 4; u++) {
                    mma_f16(sc[2*u],   qF[ks], kF[u][0], kF[u][2]);
                    mma_f16(sc[2*u+1], qF[ks], kF[u][1], kF[u][3]);
                }
            }

            // ---- base-2 online softmax ----
            float mx0 = -1e30f, mx1 = -1e30f;
#pragma unroll
            for (int ni = 0; ni < 8; ni++) {
                mx0 = fmaxf(mx0, fmaxf(sc[ni][0], sc[ni][1]));
                mx1 = fmaxf(mx1, fmaxf(sc[ni][2], sc[ni][3]));
            }
            mx0 = fmaxf(mx0, __shfl_xor_sync(0xffffffffu, mx0, 1));
            mx0 = fmaxf(mx0, __shfl_xor_sync(0xffffffffu, mx0, 2));
            mx1 = fmaxf(mx1, __shfl_xor_sync(0xffffffffu, mx1, 1));
            mx1 = fmaxf(mx1, __shfl_xor_sync(0xffffffffu, mx1, 2));
            const float mn0 = fmaxf(m0, mx0), mn1 = fmaxf(m1, mx1);
            const float al0 = ex2(m0 - mn0), al1 = ex2(m1 - mn1);
            float s0 = 0.f, s1 = 0.f;
#pragma unroll
            for (int ni = 0; ni < 8; ni++) {
                sc[ni][0] = ex2(sc[ni][0] - mn0); s0 += sc[ni][0];
                sc[ni][1] = ex2(sc[ni][1] - mn0); s0 += sc[ni][1];
                sc[ni][2] = ex2(sc[ni][2] - mn1); s1 += sc[ni][2];
                sc[ni][3] = ex2(sc[ni][3] - mn1); s1 += sc[ni][3];
            }
            s0 += __shfl_xor_sync(0xffffffffu, s0, 1);
            s0 += __shfl_xor_sync(0xffffffffu, s0, 2);
            s1 += __shfl_xor_sync(0xffffffffu, s1, 1);
            s1 += __shfl_xor_sync(0xffffffffu, s1, 2);
            l0 = l0 * al0 + s0;  l1 = l1 * al1 + s1;
            m0 = mn0;            m1 = mn1;
#pragma unroll
            for (int ni = 0; ni < 8; ni++) {
                oc[ni][0] *= al0; oc[ni][1] *= al0;
                oc[ni][2] *= al1; oc[ni][3] *= al1;
            }

            // ---- O += P V: batch 4 V-ldsm per ks, then 8 MMAs ----
#pragma unroll
            for (int ks = 0; ks < 4; ks++) {
                uint32_t ph[4];
                ph[0] = pack_h2(sc[2*ks][0],   sc[2*ks][1]);
                ph[1] = pack_h2(sc[2*ks][2],   sc[2*ks][3]);
                ph[2] = pack_h2(sc[2*ks+1][0], sc[2*ks+1][1]);
                ph[3] = pack_h2(sc[2*ks+1][2], sc[2*ks+1][3]);
                const int keyr = ks*16 + t_row;
                uint32_t vF[4][4];
#pragma unroll
                for (int pp = 0; pp < 4; pp++) {
                    const uint32_t vo = (uint32_t)(keyr * KSTR + 16*pp + t_col) * 2;
                    ldsm_x4t(vF[pp][0], vF[pp][1], vF[pp][2], vF[pp][3], uV + vo);
                }
#pragma unroll
                for (int pp = 0; pp < 4; pp++) {
                    mma_f16(oc[2*pp],   ph, vF[pp][0], vF[pp][1]);
                    mma_f16(oc[2*pp+1], ph, vF[pp][2], vF[pp][3]);
                }
            }
        }
    }

    // ---- epilogue: normalize, pack fp16, write g_att [M,E] ----
    const float inv0 = 1.f / l0, inv1 = 1.f / l1;
    const int r0row = q0 + warp*16 + (lane >> 2);
#pragma unroll
    for (int ni = 0; ni < 8; ni++) {
        const int d = ni*8 + (lane & 3)*2;
        const size_t col = (size_t)h*DD + d;
        size_t idx = (((size_t)b*SS + r0row)*EE + col) >> 1;
        ((uint32_t*)g_att)[idx] = pack_h2(oc[ni][0]*inv0, oc[ni][1]*inv0);
        idx = (((size_t)b*SS + r0row + 8)*EE + col) >> 1;
        ((uint32_t*)g_att)[idx] = pack_h2(oc[ni][2]*inv1, oc[ni][3]*inv1);
    }
}

// ---------------------------------------------------------------------------
extern "C" void kernel_launch(void* const* d_in, const int* in_sizes, int n_in,
                              void* d_out, int out_size)
{
    const float* x  = (const float*)d_in[0];
    const float* Wq = (const float*)d_in[1];
    const float* bq = (const float*)d_in[2];
    const float* Wk = (const float*)d_in[3];
    const float* bk = (const float*)d_in[4];
    const float* Wv = (const float*)d_in[5];
    const float* bv = (const float*)d_in[6];
    const float* Wo = (const float*)d_in[7];
    const float* bo = (const float*)d_in[8];
    float* out = (float*)d_out;

    conv_fused<<<(1 << 21) / 256, 256>>>(x, Wq, Wk, Wv, Wo);

    const int gsmem = 3 * 2 * GS * 2;                 // 61,440 B (3 stages)
    const int asmem = (QTILE + 2 * 4 * ATILE) * 2;    // 92,160 B
    cudaFuncSetAttribute(gemm_qkv, cudaFuncAttributeMaxDynamicSharedMemorySize, gsmem);
    cudaFuncSetAttribute(gemm_out, cudaFuncAttributeMaxDynamicSharedMemorySize, gsmem);
    cudaFuncSetAttribute(attn_mma, cudaFuncAttributeMaxDynamicSharedMemorySize, asmem);

    gemm_qkv<<<dim3(MM/128, EE/128, 3), 256, gsmem>>>(bq, bk, bv);

    attn_mma<<<dim3(SS/128, BB*HH), 256, asmem>>>();

    gemm_out<<<dim3(MM/128, EE/128), 256, gsmem>>>(bo, out);
}